// round 1
// baseline (speedup 1.0000x reference)
#include <cuda_runtime.h>

#define NN 40000
#define EE 600000
#define HH 128
#define GG 32
#define CC 6

// ---- scratch (device globals: no allocation allowed) ----
__device__ float g_b1[NN * HH];
__device__ float g_b2[NN * HH];
__device__ float g_b3[NN * HH];
__device__ float g_dinv[NN];
__device__ float g_emb[GG * HH];
__device__ float g_cnt[GG];

// ---------------- small utility kernels ----------------
__global__ void k_zero4(float* __restrict__ p, int n4) {
    int i = blockIdx.x * blockDim.x + threadIdx.x;
    if (i < n4) ((float4*)p)[i] = make_float4(0.f, 0.f, 0.f, 0.f);
}

__global__ void k_deg_init(float* __restrict__ dinv) {
    int i = blockIdx.x * blockDim.x + threadIdx.x;
    if (i < NN) dinv[i] = 1.0f;   // self-loop contributes 1
}

__global__ void k_deg_acc(const int* __restrict__ dst, float* __restrict__ dinv) {
    int e = blockIdx.x * blockDim.x + threadIdx.x;
    if (e < EE) atomicAdd(&dinv[dst[e]], 1.0f);
}

__global__ void k_deg_rsqrt(float* __restrict__ dinv) {
    int i = blockIdx.x * blockDim.x + threadIdx.x;
    if (i < NN) dinv[i] = rsqrtf(dinv[i]);
}

// out[i] = h[i] * dinv[i]^2   (GCN self-loop init), float4 over N*H
__global__ void k_selfinit(const float* __restrict__ h, const float* __restrict__ dinv,
                           float* __restrict__ out) {
    int i = blockIdx.x * blockDim.x + threadIdx.x;       // over N*H/4
    if (i >= NN * (HH / 4)) return;
    int node = i >> 5;                                    // HH/4 = 32 float4 per row
    float w = dinv[node];
    w = w * w;
    float4 v = ((const float4*)h)[i];
    v.x *= w; v.y *= w; v.z *= w; v.w *= w;
    ((float4*)out)[i] = v;
}

// h = (relu?) (h + bias)
__global__ void k_bias_act(float* __restrict__ h, const float* __restrict__ bias, int relu) {
    int i = blockIdx.x * blockDim.x + threadIdx.x;       // over N*H/4
    if (i >= NN * (HH / 4)) return;
    int col4 = (i & 31) * 4;
    float4 b = *(const float4*)(bias + col4);
    float4 v = ((float4*)h)[i];
    v.x += b.x; v.y += b.y; v.z += b.z; v.w += b.w;
    if (relu) {
        v.x = fmaxf(v.x, 0.f); v.y = fmaxf(v.y, 0.f);
        v.z = fmaxf(v.z, 0.f); v.w = fmaxf(v.w, 0.f);
    }
    ((float4*)h)[i] = v;
}

// ---------------- edge scatter: one warp per edge ----------------
// out[dst] += x[src] * (dinv ? dinv[src]*dinv[dst] : 1)
__global__ void k_scatter(const float* __restrict__ x, const int* __restrict__ src,
                          const int* __restrict__ dst, const float* __restrict__ dinv,
                          float* __restrict__ out) {
    int e = (blockIdx.x * blockDim.x + threadIdx.x) >> 5;
    int lane = threadIdx.x & 31;
    if (e >= EE) return;
    int s = src[e];
    int d = dst[e];
    float4 v = ((const float4*)(x + (size_t)s * HH))[lane];
    if (dinv) {
        float nrm = dinv[s] * dinv[d];
        v.x *= nrm; v.y *= nrm; v.z *= nrm; v.w *= nrm;
    }
    atomicAdd(((float4*)(out + (size_t)d * HH)) + lane, v);
}

// ---------------- tiled fp32 GEMM ----------------
// out[M=40000, 128] = A1 @ W1 (+ A2 @ W2) (+ bias) with optional relu
// block tile: 64 rows x 128 cols, 256 threads, each thread 4x8 outputs
#define BM 64
#define BK 32
__global__ __launch_bounds__(256) void k_gemm(
    const float* __restrict__ A1, const float* __restrict__ W1,
    const float* __restrict__ A2, const float* __restrict__ W2,
    const float* __restrict__ bias, float* __restrict__ out, int relu)
{
    __shared__ float As[BK][BM + 4];
    __shared__ float Ws[BK][HH];

    int tid = threadIdx.x;
    int ty = tid >> 4;          // 0..15 (row group)
    int tx = tid & 15;          // 0..15 (col group)
    int row0 = blockIdx.x * BM;

    float acc[4][8];
#pragma unroll
    for (int r = 0; r < 4; ++r)
#pragma unroll
        for (int c = 0; c < 8; ++c) acc[r][c] = 0.f;

#pragma unroll 1
    for (int pass = 0; pass < 2; ++pass) {
        const float* A = pass ? A2 : A1;
        const float* W = pass ? W2 : W1;
        if (A == nullptr) break;

#pragma unroll 1
        for (int k0 = 0; k0 < HH; k0 += BK) {
            // load A tile (64 x 32) transposed into As[k][m]
#pragma unroll
            for (int l = 0; l < 2; ++l) {
                int idx = tid + l * 256;          // 0..511 float4s
                int m  = idx >> 3;                // 8 float4 per row
                int kq = (idx & 7) * 4;
                float4 v = *(const float4*)(A + (size_t)(row0 + m) * HH + k0 + kq);
                As[kq + 0][m] = v.x;
                As[kq + 1][m] = v.y;
                As[kq + 2][m] = v.z;
                As[kq + 3][m] = v.w;
            }
            // load W tile (32 x 128) direct
#pragma unroll
            for (int l = 0; l < 4; ++l) {
                int idx = tid + l * 256;          // 0..1023 float4s
                int kk = idx >> 5;                // 32 float4 per row
                int nq = (idx & 31) * 4;
                *(float4*)&Ws[kk][nq] = *(const float4*)(W + (size_t)(k0 + kk) * HH + nq);
            }
            __syncthreads();

#pragma unroll
            for (int kk = 0; kk < BK; ++kk) {
                float a[4], b[8];
#pragma unroll
                for (int r = 0; r < 4; ++r) a[r] = As[kk][ty * 4 + r];
#pragma unroll
                for (int c = 0; c < 8; ++c) b[c] = Ws[kk][tx * 8 + c];
#pragma unroll
                for (int r = 0; r < 4; ++r)
#pragma unroll
                    for (int c = 0; c < 8; ++c) acc[r][c] = fmaf(a[r], b[c], acc[r][c]);
            }
            __syncthreads();
        }
    }

#pragma unroll
    for (int r = 0; r < 4; ++r) {
        int m = row0 + ty * 4 + r;
#pragma unroll
        for (int c = 0; c < 8; c += 4) {
            int n = tx * 8 + c;
            float4 v = make_float4(acc[r][c], acc[r][c + 1], acc[r][c + 2], acc[r][c + 3]);
            if (bias) {
                float4 bb = *(const float4*)(bias + n);
                v.x += bb.x; v.y += bb.y; v.z += bb.z; v.w += bb.w;
            }
            if (relu) {
                v.x = fmaxf(v.x, 0.f); v.y = fmaxf(v.y, 0.f);
                v.z = fmaxf(v.z, 0.f); v.w = fmaxf(v.w, 0.f);
            }
            *(float4*)(out + (size_t)m * HH + n) = v;
        }
    }
}

// ---------------- pooling: one warp per node ----------------
__global__ void k_pool(const float* __restrict__ h, const int* __restrict__ batch,
                       float* __restrict__ emb, float* __restrict__ cnt) {
    int i = (blockIdx.x * blockDim.x + threadIdx.x) >> 5;
    int lane = threadIdx.x & 31;
    if (i >= NN) return;
    int g = batch[i];
    float4 v = ((const float4*)(h + (size_t)i * HH))[lane];
    atomicAdd(((float4*)(emb + (size_t)g * HH)) + lane, v);
    if (lane == 0) atomicAdd(&cnt[g], 1.0f);
}

// ---------------- final head: mean + linear ----------------
__global__ void k_final(const float* __restrict__ lin_w, const float* __restrict__ lin_b,
                        const float* __restrict__ emb, const float* __restrict__ cnt,
                        float* __restrict__ out) {
    __shared__ float se[GG * HH];
    int tid = threadIdx.x;
    for (int i = tid; i < GG * HH; i += blockDim.x) {
        int g = i >> 7;
        float v = emb[i] / fmaxf(cnt[g], 1.0f);
        se[i] = v;
        out[GG * CC + i] = v;          // embedding goes after logits
    }
    __syncthreads();
    for (int i = tid; i < GG * CC; i += blockDim.x) {
        int g = i / CC, c = i % CC;
        float s = lin_b[c];
        const float* e = &se[g * HH];
#pragma unroll 4
        for (int k = 0; k < HH; ++k) s = fmaf(e[k], lin_w[k * CC + c], s);
        out[i] = s;
    }
}

// ---------------- launch ----------------
extern "C" void kernel_launch(void* const* d_in, const int* in_sizes, int n_in,
                              void* d_out, int out_size) {
    const float* x      = (const float*)d_in[0];
    const int*   ei     = (const int*)d_in[1];
    const int*   batch  = (const int*)d_in[2];
    const float* w1r    = (const float*)d_in[3];
    const float* w1rel  = (const float*)d_in[4];
    const float* b1     = (const float*)d_in[5];
    const float* w2r    = (const float*)d_in[6];
    const float* w2rel  = (const float*)d_in[7];
    const float* b2     = (const float*)d_in[8];
    const float* w3     = (const float*)d_in[9];
    const float* b3     = (const float*)d_in[10];
    const float* w4     = (const float*)d_in[11];
    const float* b4     = (const float*)d_in[12];
    const float* w5     = (const float*)d_in[13];
    const float* b5     = (const float*)d_in[14];
    const float* lin_w  = (const float*)d_in[15];
    const float* lin_b  = (const float*)d_in[16];
    float* out = (float*)d_out;

    const int* src = ei;
    const int* dst = ei + EE;

    float *B1, *B2, *B3, *DINV, *EMB, *CNT;
    cudaGetSymbolAddress((void**)&B1, g_b1);
    cudaGetSymbolAddress((void**)&B2, g_b2);
    cudaGetSymbolAddress((void**)&B3, g_b3);
    cudaGetSymbolAddress((void**)&DINV, g_dinv);
    cudaGetSymbolAddress((void**)&EMB, g_emb);
    cudaGetSymbolAddress((void**)&CNT, g_cnt);

    const int NH4 = NN * HH / 4;               // 1,280,000
    const int ZB  = (NH4 + 255) / 256;
    const int NB  = (NN + 255) / 256;
    const int EB  = (EE + 255) / 256;
    const int SCB = EE * 32 / 256;             // 75000 (exact)
    const int GMB = NN / BM;                   // 625 (exact)

    // degrees (with self-loop) -> dinv = rsqrt(deg)
    k_deg_init<<<NB, 256>>>(DINV);
    k_deg_acc<<<EB, 256>>>(dst, DINV);
    k_deg_rsqrt<<<NB, 256>>>(DINV);

    // ---- Layer 1: GraphConv ----
    k_zero4<<<ZB, 256>>>(B1, NH4);
    k_scatter<<<SCB, 256>>>(x, src, dst, nullptr, B1);
    k_gemm<<<GMB, 256>>>(x, w1r, B1, w1rel, b1, B2, 1);

    // ---- Layer 2: GraphConv ----
    k_zero4<<<ZB, 256>>>(B1, NH4);
    k_scatter<<<SCB, 256>>>(B2, src, dst, nullptr, B1);
    k_gemm<<<GMB, 256>>>(B2, w2r, B1, w2rel, b2, B3, 1);

    // ---- Layer 3: GCNConv ----
    k_gemm<<<GMB, 256>>>(B3, w3, nullptr, nullptr, nullptr, B2, 0);
    k_selfinit<<<ZB, 256>>>(B2, DINV, B1);
    k_scatter<<<SCB, 256>>>(B2, src, dst, DINV, B1);
    k_bias_act<<<ZB, 256>>>(B1, b3, 1);

    // ---- Layer 4: GCNConv ----
    k_gemm<<<GMB, 256>>>(B1, w4, nullptr, nullptr, nullptr, B2, 0);
    k_selfinit<<<ZB, 256>>>(B2, DINV, B3);
    k_scatter<<<SCB, 256>>>(B2, src, dst, DINV, B3);
    k_bias_act<<<ZB, 256>>>(B3, b4, 1);

    // ---- Layer 5: GCNConv (no relu) ----
    k_gemm<<<GMB, 256>>>(B3, w5, nullptr, nullptr, nullptr, B2, 0);
    k_selfinit<<<ZB, 256>>>(B2, DINV, B1);
    k_scatter<<<SCB, 256>>>(B2, src, dst, DINV, B1);
    k_bias_act<<<ZB, 256>>>(B1, b5, 0);

    // ---- pooling + head ----
    k_zero4<<<(GG * HH / 4 + 255) / 256, 256>>>(EMB, GG * HH / 4);
    k_zero4<<<1, 32>>>(CNT, GG / 4);
    k_pool<<<NN * 32 / 256, 256>>>(B1, batch, EMB, CNT);
    k_final<<<1, 512>>>(lin_w, lin_b, EMB, CNT, out);
}

// round 2
// speedup vs baseline: 1.3117x; 1.3117x over previous
#include <cuda_runtime.h>

#define NN 40000
#define EE 600000
#define HH 128
#define GG 32
#define CC 6

// ---- scratch (device globals: no allocation allowed) ----
__device__ float g_b1[NN * HH];
__device__ float g_b2[NN * HH];
__device__ float g_b3[NN * HH];
__device__ float g_dinv[NN];
__device__ float g_emb[GG * HH];
__device__ float g_cnt[GG];

// ---------------- small utility kernels ----------------
__global__ void k_zero4(float* __restrict__ p, int n4) {
    int i = blockIdx.x * blockDim.x + threadIdx.x;
    if (i < n4) ((float4*)p)[i] = make_float4(0.f, 0.f, 0.f, 0.f);
}

__global__ void k_deg_init(float* __restrict__ dinv) {
    int i = blockIdx.x * blockDim.x + threadIdx.x;
    if (i < NN) dinv[i] = 1.0f;   // self-loop contributes 1
}

__global__ void k_deg_acc(const int* __restrict__ dst, float* __restrict__ dinv) {
    int e = blockIdx.x * blockDim.x + threadIdx.x;
    if (e < EE) atomicAdd(&dinv[dst[e]], 1.0f);
}

__global__ void k_deg_rsqrt(float* __restrict__ dinv) {
    int i = blockIdx.x * blockDim.x + threadIdx.x;
    if (i < NN) dinv[i] = rsqrtf(dinv[i]);
}

// ---------------- edge scatter: one warp per edge ----------------
__global__ void k_scatter(const float* __restrict__ x, const int* __restrict__ src,
                          const int* __restrict__ dst, const float* __restrict__ dinv,
                          float* __restrict__ out) {
    int e = (blockIdx.x * blockDim.x + threadIdx.x) >> 5;
    int lane = threadIdx.x & 31;
    if (e >= EE) return;
    int s = src[e];
    int d = dst[e];
    float4 v = ((const float4*)(x + (size_t)s * HH))[lane];
    if (dinv) {
        float nrm = dinv[s] * dinv[d];
        v.x *= nrm; v.y *= nrm; v.z *= nrm; v.w *= nrm;
    }
    atomicAdd(((float4*)(out + (size_t)d * HH)) + lane, v);
}

// ---------------- 3xTF32 tensor-core GEMM ----------------
// out[40000,128] = (act(A1+bias_in)) @ W1 (+ A2 @ W2)
// epilogue: if dinv: out1 = acc (raw), out2 = acc*dinv[m]^2
//           else:    out1 = (relu?)(acc + bias_out); if out2: out2 = 0
// CTA tile: 128x128, BK=32, 256 threads (8 warps, 4x2 grid, warp tile 32x64)

__device__ __forceinline__ unsigned f2tf(float f) {
    unsigned u;
    asm("cvt.rna.tf32.f32 %0, %1;" : "=r"(u) : "f"(f));
    return u;
}

__device__ __forceinline__ void mma_tf32(float (&c)[4], const unsigned (&a)[4],
                                         unsigned b0, unsigned b1) {
    asm volatile(
        "mma.sync.aligned.m16n8k8.row.col.f32.tf32.tf32.f32 "
        "{%0,%1,%2,%3},{%4,%5,%6,%7},{%8,%9},{%0,%1,%2,%3};"
        : "+f"(c[0]), "+f"(c[1]), "+f"(c[2]), "+f"(c[3])
        : "r"(a[0]), "r"(a[1]), "r"(a[2]), "r"(a[3]), "r"(b0), "r"(b1));
}

#define AP 36   // A smem pitch (=> bank pattern 4g+t, conflict-free)
#define WP 136  // W smem pitch (=> bank pattern 8t+g, conflict-free)
#define ASZ (128 * AP)
#define WSZ (32 * WP)

__global__ __launch_bounds__(256, 2) void k_gemm_tc(
    const float* __restrict__ A1, const float* __restrict__ W1,
    const float* __restrict__ A2, const float* __restrict__ W2,
    const float* __restrict__ bias_in,   // applied (with relu) to A1 load
    const float* __restrict__ bias_out,
    const float* __restrict__ dinv,
    float* __restrict__ out1, float* __restrict__ out2, int relu_out)
{
    extern __shared__ unsigned sm[];
    unsigned* AH = sm;
    unsigned* AL = AH + ASZ;
    unsigned* WH = AL + ASZ;
    unsigned* WL = WH + WSZ;

    const int tid = threadIdx.x;
    const int wid = tid >> 5;
    const int lane = tid & 31;
    const int g = lane >> 2;
    const int t = lane & 3;
    const int warpM = wid >> 1;       // 0..3
    const int warpN = wid & 1;        // 0..1
    const int row0 = blockIdx.x * 128;

    float acc[2][8][4];
#pragma unroll
    for (int mi = 0; mi < 2; ++mi)
#pragma unroll
        for (int ni = 0; ni < 8; ++ni)
#pragma unroll
            for (int j = 0; j < 4; ++j) acc[mi][ni][j] = 0.f;

    const int npass = A2 ? 2 : 1;
#pragma unroll 1
    for (int p = 0; p < npass; ++p) {
        const float* A = p ? A2 : A1;
        const float* W = p ? W2 : W1;
        const bool pre = (p == 0) && (bias_in != nullptr);

#pragma unroll 1
        for (int k0 = 0; k0 < HH; k0 += 32) {
            __syncthreads();
            // load A tile (128 x 32)
#pragma unroll
            for (int i = 0; i < 4; ++i) {
                int idx = tid + i * 256;
                int r = idx >> 3;
                int c4 = (idx & 7) * 4;
                int grow = row0 + r;
                float4 v = make_float4(0.f, 0.f, 0.f, 0.f);
                if (grow < NN) v = *(const float4*)(A + (size_t)grow * HH + k0 + c4);
                if (pre) {
                    v.x = fmaxf(v.x + bias_in[k0 + c4 + 0], 0.f);
                    v.y = fmaxf(v.y + bias_in[k0 + c4 + 1], 0.f);
                    v.z = fmaxf(v.z + bias_in[k0 + c4 + 2], 0.f);
                    v.w = fmaxf(v.w + bias_in[k0 + c4 + 3], 0.f);
                }
                int bo = r * AP + c4;
                float vv[4] = {v.x, v.y, v.z, v.w};
#pragma unroll
                for (int j = 0; j < 4; ++j) {
                    unsigned h = f2tf(vv[j]);
                    AH[bo + j] = h;
                    AL[bo + j] = f2tf(vv[j] - __uint_as_float(h));
                }
            }
            // load W tile (32 x 128)
#pragma unroll
            for (int i = 0; i < 4; ++i) {
                int idx = tid + i * 256;
                int k = idx >> 5;
                int c4 = (idx & 31) * 4;
                float4 v = *(const float4*)(W + (size_t)(k0 + k) * HH + c4);
                int bo = k * WP + c4;
                float vv[4] = {v.x, v.y, v.z, v.w};
#pragma unroll
                for (int j = 0; j < 4; ++j) {
                    unsigned h = f2tf(vv[j]);
                    WH[bo + j] = h;
                    WL[bo + j] = f2tf(vv[j] - __uint_as_float(h));
                }
            }
            __syncthreads();

#pragma unroll
            for (int ks = 0; ks < 4; ++ks) {
                int kb = ks * 8;
                unsigned ah[2][4], al[2][4];
#pragma unroll
                for (int mi = 0; mi < 2; ++mi) {
                    int rb = (warpM * 32 + mi * 16 + g) * AP + kb + t;
                    ah[mi][0] = AH[rb];
                    ah[mi][1] = AH[rb + 8 * AP];
                    ah[mi][2] = AH[rb + 4];
                    ah[mi][3] = AH[rb + 8 * AP + 4];
                    al[mi][0] = AL[rb];
                    al[mi][1] = AL[rb + 8 * AP];
                    al[mi][2] = AL[rb + 4];
                    al[mi][3] = AL[rb + 8 * AP + 4];
                }
#pragma unroll
                for (int ni = 0; ni < 8; ++ni) {
                    int col = warpN * 64 + ni * 8 + g;
                    int wb = (kb + t) * WP + col;
                    unsigned bh0 = WH[wb], bh1 = WH[wb + 4 * WP];
                    unsigned bl0 = WL[wb], bl1 = WL[wb + 4 * WP];
#pragma unroll
                    for (int mi = 0; mi < 2; ++mi) {
                        mma_tf32(acc[mi][ni], ah[mi], bh0, bh1);
                        mma_tf32(acc[mi][ni], ah[mi], bl0, bl1);
                        mma_tf32(acc[mi][ni], al[mi], bh0, bh1);
                    }
                }
            }
        }
    }

    // epilogue
#pragma unroll
    for (int mi = 0; mi < 2; ++mi) {
        int rbase = row0 + warpM * 32 + mi * 16 + g;
#pragma unroll
        for (int ni = 0; ni < 8; ++ni) {
            int col = warpN * 64 + ni * 8 + 2 * t;
            float c0 = acc[mi][ni][0], c1 = acc[mi][ni][1];
            float c2 = acc[mi][ni][2], c3 = acc[mi][ni][3];
            if (dinv) {
                if (rbase < NN) {
                    float w = dinv[rbase]; w *= w;
                    *(float2*)(out1 + (size_t)rbase * HH + col) = make_float2(c0, c1);
                    *(float2*)(out2 + (size_t)rbase * HH + col) = make_float2(c0 * w, c1 * w);
                }
                if (rbase + 8 < NN) {
                    float w = dinv[rbase + 8]; w *= w;
                    *(float2*)(out1 + (size_t)(rbase + 8) * HH + col) = make_float2(c2, c3);
                    *(float2*)(out2 + (size_t)(rbase + 8) * HH + col) = make_float2(c2 * w, c3 * w);
                }
            } else {
                float b0 = bias_out[col], b1 = bias_out[col + 1];
                c0 += b0; c1 += b1; c2 += b0; c3 += b1;
                if (relu_out) {
                    c0 = fmaxf(c0, 0.f); c1 = fmaxf(c1, 0.f);
                    c2 = fmaxf(c2, 0.f); c3 = fmaxf(c3, 0.f);
                }
                if (rbase < NN) {
                    *(float2*)(out1 + (size_t)rbase * HH + col) = make_float2(c0, c1);
                    if (out2) *(float2*)(out2 + (size_t)rbase * HH + col) = make_float2(0.f, 0.f);
                }
                if (rbase + 8 < NN) {
                    *(float2*)(out1 + (size_t)(rbase + 8) * HH + col) = make_float2(c2, c3);
                    if (out2) *(float2*)(out2 + (size_t)(rbase + 8) * HH + col) = make_float2(0.f, 0.f);
                }
            }
        }
    }
}

// ---------------- pooling: one warp per node ----------------
__global__ void k_pool(const float* __restrict__ h, const int* __restrict__ batch,
                       float* __restrict__ emb, float* __restrict__ cnt) {
    int i = (blockIdx.x * blockDim.x + threadIdx.x) >> 5;
    int lane = threadIdx.x & 31;
    if (i >= NN) return;
    int g = batch[i];
    float4 v = ((const float4*)(h + (size_t)i * HH))[lane];
    atomicAdd(((float4*)(emb + (size_t)g * HH)) + lane, v);
    if (lane == 0) atomicAdd(&cnt[g], 1.0f);
}

// ---------------- final head: mean (+b5) + linear ----------------
__global__ void k_final(const float* __restrict__ lin_w, const float* __restrict__ lin_b,
                        const float* __restrict__ b5,
                        const float* __restrict__ emb, const float* __restrict__ cnt,
                        float* __restrict__ out) {
    __shared__ float se[GG * HH];
    int tid = threadIdx.x;
    for (int i = tid; i < GG * HH; i += blockDim.x) {
        int g = i >> 7;
        int c = i & 127;
        float v = emb[i] / fmaxf(cnt[g], 1.0f) + b5[c];
        se[i] = v;
        out[GG * CC + i] = v;          // embedding goes after logits
    }
    __syncthreads();
    for (int i = tid; i < GG * CC; i += blockDim.x) {
        int g = i / CC, c = i % CC;
        float s = lin_b[c];
        const float* e = &se[g * HH];
#pragma unroll 4
        for (int k = 0; k < HH; ++k) s = fmaf(e[k], lin_w[k * CC + c], s);
        out[i] = s;
    }
}

// ---------------- launch ----------------
extern "C" void kernel_launch(void* const* d_in, const int* in_sizes, int n_in,
                              void* d_out, int out_size) {
    const float* x      = (const float*)d_in[0];
    const int*   ei     = (const int*)d_in[1];
    const int*   batch  = (const int*)d_in[2];
    const float* w1r    = (const float*)d_in[3];
    const float* w1rel  = (const float*)d_in[4];
    const float* b1     = (const float*)d_in[5];
    const float* w2r    = (const float*)d_in[6];
    const float* w2rel  = (const float*)d_in[7];
    const float* b2     = (const float*)d_in[8];
    const float* w3     = (const float*)d_in[9];
    const float* b3     = (const float*)d_in[10];
    const float* w4     = (const float*)d_in[11];
    const float* b4     = (const float*)d_in[12];
    const float* w5     = (const float*)d_in[13];
    const float* b5     = (const float*)d_in[14];
    const float* lin_w  = (const float*)d_in[15];
    const float* lin_b  = (const float*)d_in[16];
    float* out = (float*)d_out;

    const int* src = ei;
    const int* dst = ei + EE;

    float *B1, *B2, *B3, *DINV, *EMB, *CNT;
    cudaGetSymbolAddress((void**)&B1, g_b1);
    cudaGetSymbolAddress((void**)&B2, g_b2);
    cudaGetSymbolAddress((void**)&B3, g_b3);
    cudaGetSymbolAddress((void**)&DINV, g_dinv);
    cudaGetSymbolAddress((void**)&EMB, g_emb);
    cudaGetSymbolAddress((void**)&CNT, g_cnt);

    const int SMEM = (2 * ASZ + 2 * WSZ) * 4;   // 71680 B
    cudaFuncSetAttribute(k_gemm_tc, cudaFuncAttributeMaxDynamicSharedMemorySize, SMEM);

    const int NH4 = NN * HH / 4;
    const int ZB  = (NH4 + 255) / 256;
    const int NB  = (NN + 255) / 256;
    const int EB  = (EE + 255) / 256;
    const int SCB = EE * 32 / 256;             // 75000
    const int GMB = (NN + 127) / 128;          // 313

    // degrees (with self-loop) -> dinv = rsqrt(deg)
    k_deg_init<<<NB, 256>>>(DINV);
    k_deg_acc<<<EB, 256>>>(dst, DINV);
    k_deg_rsqrt<<<NB, 256>>>(DINV);

    // ---- L1: GraphConv ----
    k_zero4<<<ZB, 256>>>(B1, NH4);
    k_scatter<<<SCB, 256>>>(x, src, dst, nullptr, B1);
    // out1 = relu(x@w1r + agg@w1rel + b1) -> B2 ; out2 = zeros -> B3 (L2 accumulator)
    k_gemm_tc<<<GMB, 256, SMEM>>>(x, w1r, B1, w1rel, nullptr, b1, nullptr, B2, B3, 1);

    // ---- L2: GraphConv ----
    k_scatter<<<SCB, 256>>>(B2, src, dst, nullptr, B3);
    k_gemm_tc<<<GMB, 256, SMEM>>>(B2, w2r, B3, w2rel, nullptr, b2, nullptr, B1, nullptr, 1);

    // ---- L3: GCNConv ----
    // raw h3 -> B2, selfinit h3*dinv^2 -> B3
    k_gemm_tc<<<GMB, 256, SMEM>>>(B1, w3, nullptr, nullptr, nullptr, nullptr, DINV, B2, B3, 0);
    k_scatter<<<SCB, 256>>>(B2, src, dst, DINV, B3);

    // ---- L4: GCNConv (input gets +b3, relu on load) ----
    k_gemm_tc<<<GMB, 256, SMEM>>>(B3, w4, nullptr, nullptr, b3, nullptr, DINV, B2, B1, 0);
    k_scatter<<<SCB, 256>>>(B2, src, dst, DINV, B1);

    // ---- L5: GCNConv (input gets +b4, relu on load) ----
    k_gemm_tc<<<GMB, 256, SMEM>>>(B1, w5, nullptr, nullptr, b4, nullptr, DINV, B2, B3, 0);
    k_scatter<<<SCB, 256>>>(B2, src, dst, DINV, B3);

    // ---- pooling + head (b5 folded into final mean) ----
    k_zero4<<<(GG * HH / 4 + 255) / 256, 256>>>(EMB, GG * HH / 4);
    k_zero4<<<1, 32>>>(CNT, GG / 4);
    k_pool<<<NN * 32 / 256, 256>>>(B3, batch, EMB, CNT);
    k_final<<<1, 512>>>(lin_w, lin_b, b5, EMB, CNT, out);
}

// round 3
// speedup vs baseline: 1.5776x; 1.2027x over previous
#include <cuda_runtime.h>

#define NN 40000
#define EE 600000
#define HH 128
#define GG 32
#define CC 6

// ---- scratch (device globals: no allocation allowed) ----
__device__ float g_b1[NN * HH];
__device__ float g_b2[NN * HH];
__device__ float g_b3[NN * HH];
__device__ float g_dinv[NN];
__device__ float g_emb[GG * HH];
__device__ float g_cnt[GG];
__device__ int   g_deg[NN];
__device__ int   g_rowstart[NN + 1];
__device__ int   g_cursor[NN];
__device__ int   g_csrsrc[EE];
__device__ float g_wnorm[EE];

// ---------------- small utility kernels ----------------
__global__ void k_zero4(float* __restrict__ p, int n4) {
    int i = blockIdx.x * blockDim.x + threadIdx.x;
    if (i < n4) ((float4*)p)[i] = make_float4(0.f, 0.f, 0.f, 0.f);
}

__global__ void k_zero_int(int* __restrict__ p, int n) {
    int i = blockIdx.x * blockDim.x + threadIdx.x;
    if (i < n) p[i] = 0;
}

__global__ void k_hist(const int* __restrict__ dst, int* __restrict__ cnt) {
    int e = blockIdx.x * blockDim.x + threadIdx.x;
    if (e < EE) atomicAdd(&cnt[dst[e]], 1);
}

// single block, 1024 threads: exclusive scan of deg -> row_start, cursor; dinv = rsqrt(deg+1)
__global__ __launch_bounds__(1024) void k_scan(const int* __restrict__ cnt,
                                               int* __restrict__ row_start,
                                               int* __restrict__ cursor,
                                               float* __restrict__ dinv) {
    __shared__ int s[1024];
    const int CH = 40;                       // 1024*40 >= 40000
    int t = threadIdx.x;
    int base = t * CH;
    int sum = 0;
#pragma unroll
    for (int i = 0; i < CH; ++i) {
        int idx = base + i;
        if (idx < NN) sum += cnt[idx];
    }
    s[t] = sum;
    __syncthreads();
#pragma unroll
    for (int off = 1; off < 1024; off <<= 1) {
        int v = 0;
        if (t >= off) v = s[t - off];
        __syncthreads();
        if (t >= off) s[t] += v;
        __syncthreads();
    }
    int pre = (t == 0) ? 0 : s[t - 1];
#pragma unroll
    for (int i = 0; i < CH; ++i) {
        int idx = base + i;
        if (idx < NN) {
            row_start[idx] = pre;
            cursor[idx] = pre;
            dinv[idx] = rsqrtf((float)(cnt[idx] + 1));
            pre += cnt[idx];
        }
    }
    if (t == 1023) row_start[NN] = EE;
}

__global__ void k_fill(const int* __restrict__ src, const int* __restrict__ dst,
                       const float* __restrict__ dinv,
                       int* __restrict__ cursor, int* __restrict__ csr_src,
                       float* __restrict__ wnorm) {
    int e = blockIdx.x * blockDim.x + threadIdx.x;
    if (e >= EE) return;
    int s = src[e];
    int d = dst[e];
    int pos = atomicAdd(&cursor[d], 1);
    csr_src[pos] = s;
    wnorm[pos] = dinv[s] * dinv[d];
}

// ---------------- gather aggregation: one warp per node ----------------
// wnorm==null:  out[node] = sum_{s in N(node)} x[s]                    (overwrite)
// wnorm!=null:  out[node] = out[node] + sum wnorm[e]*x[s]              (in-place add)
__global__ __launch_bounds__(256) void k_gather(
    const float* __restrict__ x, float* __restrict__ out,
    const int* __restrict__ row_start, const int* __restrict__ csr_src,
    const float* __restrict__ wnorm)
{
    int node = (blockIdx.x * blockDim.x + threadIdx.x) >> 5;
    int lane = threadIdx.x & 31;
    if (node >= NN) return;
    int beg = row_start[node];
    int end = row_start[node + 1];

    float4 acc = make_float4(0.f, 0.f, 0.f, 0.f);
    int e = beg;
    // unroll-by-2 to get two rows in flight
    for (; e + 1 < end; e += 2) {
        int s0 = csr_src[e], s1 = csr_src[e + 1];
        float4 v0 = ((const float4*)(x + (size_t)s0 * HH))[lane];
        float4 v1 = ((const float4*)(x + (size_t)s1 * HH))[lane];
        float w0 = 1.f, w1 = 1.f;
        if (wnorm) { w0 = wnorm[e]; w1 = wnorm[e + 1]; }
        acc.x = fmaf(v0.x, w0, acc.x); acc.y = fmaf(v0.y, w0, acc.y);
        acc.z = fmaf(v0.z, w0, acc.z); acc.w = fmaf(v0.w, w0, acc.w);
        acc.x = fmaf(v1.x, w1, acc.x); acc.y = fmaf(v1.y, w1, acc.y);
        acc.z = fmaf(v1.z, w1, acc.z); acc.w = fmaf(v1.w, w1, acc.w);
    }
    if (e < end) {
        int s0 = csr_src[e];
        float4 v0 = ((const float4*)(x + (size_t)s0 * HH))[lane];
        float w0 = wnorm ? wnorm[e] : 1.f;
        acc.x = fmaf(v0.x, w0, acc.x); acc.y = fmaf(v0.y, w0, acc.y);
        acc.z = fmaf(v0.z, w0, acc.z); acc.w = fmaf(v0.w, w0, acc.w);
    }

    float4* o = ((float4*)(out + (size_t)node * HH)) + lane;
    if (wnorm) {
        float4 cur = *o;
        acc.x += cur.x; acc.y += cur.y; acc.z += cur.z; acc.w += cur.w;
    }
    *o = acc;
}

// ---------------- 3xTF32 tensor-core GEMM ----------------
__device__ __forceinline__ unsigned f2tf(float f) {
    unsigned u;
    asm("cvt.rna.tf32.f32 %0, %1;" : "=r"(u) : "f"(f));
    return u;
}

__device__ __forceinline__ void mma_tf32(float (&c)[4], const unsigned (&a)[4],
                                         unsigned b0, unsigned b1) {
    asm volatile(
        "mma.sync.aligned.m16n8k8.row.col.f32.tf32.tf32.f32 "
        "{%0,%1,%2,%3},{%4,%5,%6,%7},{%8,%9},{%0,%1,%2,%3};"
        : "+f"(c[0]), "+f"(c[1]), "+f"(c[2]), "+f"(c[3])
        : "r"(a[0]), "r"(a[1]), "r"(a[2]), "r"(a[3]), "r"(b0), "r"(b1));
}

#define AP 36
#define WP 136
#define ASZ (128 * AP)
#define WSZ (32 * WP)

__global__ __launch_bounds__(256, 2) void k_gemm_tc(
    const float* __restrict__ A1, const float* __restrict__ W1,
    const float* __restrict__ A2, const float* __restrict__ W2,
    const float* __restrict__ bias_in,   // applied (with relu) to A1 load
    const float* __restrict__ bias_out,
    const float* __restrict__ dinv,
    float* __restrict__ out1, float* __restrict__ out2, int relu_out)
{
    extern __shared__ unsigned sm[];
    unsigned* AH = sm;
    unsigned* AL = AH + ASZ;
    unsigned* WH = AL + ASZ;
    unsigned* WL = WH + WSZ;

    const int tid = threadIdx.x;
    const int wid = tid >> 5;
    const int lane = tid & 31;
    const int g = lane >> 2;
    const int t = lane & 3;
    const int warpM = wid >> 1;
    const int warpN = wid & 1;
    const int row0 = blockIdx.x * 128;

    float acc[2][8][4];
#pragma unroll
    for (int mi = 0; mi < 2; ++mi)
#pragma unroll
        for (int ni = 0; ni < 8; ++ni)
#pragma unroll
            for (int j = 0; j < 4; ++j) acc[mi][ni][j] = 0.f;

    const int npass = A2 ? 2 : 1;
#pragma unroll 1
    for (int p = 0; p < npass; ++p) {
        const float* A = p ? A2 : A1;
        const float* W = p ? W2 : W1;
        const bool pre = (p == 0) && (bias_in != nullptr);

#pragma unroll 1
        for (int k0 = 0; k0 < HH; k0 += 32) {
            __syncthreads();
#pragma unroll
            for (int i = 0; i < 4; ++i) {
                int idx = tid + i * 256;
                int r = idx >> 3;
                int c4 = (idx & 7) * 4;
                int grow = row0 + r;
                float4 v = make_float4(0.f, 0.f, 0.f, 0.f);
                if (grow < NN) v = *(const float4*)(A + (size_t)grow * HH + k0 + c4);
                if (pre) {
                    v.x = fmaxf(v.x + bias_in[k0 + c4 + 0], 0.f);
                    v.y = fmaxf(v.y + bias_in[k0 + c4 + 1], 0.f);
                    v.z = fmaxf(v.z + bias_in[k0 + c4 + 2], 0.f);
                    v.w = fmaxf(v.w + bias_in[k0 + c4 + 3], 0.f);
                }
                int bo = r * AP + c4;
                float vv[4] = {v.x, v.y, v.z, v.w};
#pragma unroll
                for (int j = 0; j < 4; ++j) {
                    unsigned h = f2tf(vv[j]);
                    AH[bo + j] = h;
                    AL[bo + j] = f2tf(vv[j] - __uint_as_float(h));
                }
            }
#pragma unroll
            for (int i = 0; i < 4; ++i) {
                int idx = tid + i * 256;
                int k = idx >> 5;
                int c4 = (idx & 31) * 4;
                float4 v = *(const float4*)(W + (size_t)(k0 + k) * HH + c4);
                int bo = k * WP + c4;
                float vv[4] = {v.x, v.y, v.z, v.w};
#pragma unroll
                for (int j = 0; j < 4; ++j) {
                    unsigned h = f2tf(vv[j]);
                    WH[bo + j] = h;
                    WL[bo + j] = f2tf(vv[j] - __uint_as_float(h));
                }
            }
            __syncthreads();

#pragma unroll
            for (int ks = 0; ks < 4; ++ks) {
                int kb = ks * 8;
                unsigned ah[2][4], al[2][4];
#pragma unroll
                for (int mi = 0; mi < 2; ++mi) {
                    int rb = (warpM * 32 + mi * 16 + g) * AP + kb + t;
                    ah[mi][0] = AH[rb];
                    ah[mi][1] = AH[rb + 8 * AP];
                    ah[mi][2] = AH[rb + 4];
                    ah[mi][3] = AH[rb + 8 * AP + 4];
                    al[mi][0] = AL[rb];
                    al[mi][1] = AL[rb + 8 * AP];
                    al[mi][2] = AL[rb + 4];
                    al[mi][3] = AL[rb + 8 * AP + 4];
                }
#pragma unroll
                for (int ni = 0; ni < 8; ++ni) {
                    int col = warpN * 64 + ni * 8 + g;
                    int wb = (kb + t) * WP + col;
                    unsigned bh0 = WH[wb], bh1 = WH[wb + 4 * WP];
                    unsigned bl0 = WL[wb], bl1 = WL[wb + 4 * WP];
#pragma unroll
                    for (int mi = 0; mi < 2; ++mi) {
                        mma_tf32(acc[mi][ni], ah[mi], bh0, bh1);
                        mma_tf32(acc[mi][ni], ah[mi], bl0, bl1);
                        mma_tf32(acc[mi][ni], al[mi], bh0, bh1);
                    }
                }
            }
        }
    }

#pragma unroll
    for (int mi = 0; mi < 2; ++mi) {
        int rbase = row0 + warpM * 32 + mi * 16 + g;
#pragma unroll
        for (int ni = 0; ni < 8; ++ni) {
            int col = warpN * 64 + ni * 8 + 2 * t;
            float c0 = acc[mi][ni][0], c1 = acc[mi][ni][1];
            float c2 = acc[mi][ni][2], c3 = acc[mi][ni][3];
            if (dinv) {
                if (rbase < NN) {
                    float w = dinv[rbase]; w *= w;
                    *(float2*)(out1 + (size_t)rbase * HH + col) = make_float2(c0, c1);
                    *(float2*)(out2 + (size_t)rbase * HH + col) = make_float2(c0 * w, c1 * w);
                }
                if (rbase + 8 < NN) {
                    float w = dinv[rbase + 8]; w *= w;
                    *(float2*)(out1 + (size_t)(rbase + 8) * HH + col) = make_float2(c2, c3);
                    *(float2*)(out2 + (size_t)(rbase + 8) * HH + col) = make_float2(c2 * w, c3 * w);
                }
            } else {
                float b0 = bias_out[col], b1 = bias_out[col + 1];
                c0 += b0; c1 += b1; c2 += b0; c3 += b1;
                if (relu_out) {
                    c0 = fmaxf(c0, 0.f); c1 = fmaxf(c1, 0.f);
                    c2 = fmaxf(c2, 0.f); c3 = fmaxf(c3, 0.f);
                }
                if (rbase < NN)
                    *(float2*)(out1 + (size_t)rbase * HH + col) = make_float2(c0, c1);
                if (rbase + 8 < NN)
                    *(float2*)(out1 + (size_t)(rbase + 8) * HH + col) = make_float2(c2, c3);
            }
        }
    }
}

// ---------------- pooling: one warp per node ----------------
__global__ void k_pool(const float* __restrict__ h, const int* __restrict__ batch,
                       float* __restrict__ emb, float* __restrict__ cnt) {
    int i = (blockIdx.x * blockDim.x + threadIdx.x) >> 5;
    int lane = threadIdx.x & 31;
    if (i >= NN) return;
    int g = batch[i];
    float4 v = ((const float4*)(h + (size_t)i * HH))[lane];
    atomicAdd(((float4*)(emb + (size_t)g * HH)) + lane, v);
    if (lane == 0) atomicAdd(&cnt[g], 1.0f);
}

// ---------------- final head: mean (+b5) + linear ----------------
__global__ void k_final(const float* __restrict__ lin_w, const float* __restrict__ lin_b,
                        const float* __restrict__ b5,
                        const float* __restrict__ emb, const float* __restrict__ cnt,
                        float* __restrict__ out) {
    __shared__ float se[GG * HH];
    int tid = threadIdx.x;
    for (int i = tid; i < GG * HH; i += blockDim.x) {
        int g = i >> 7;
        int c = i & 127;
        float v = emb[i] / fmaxf(cnt[g], 1.0f) + b5[c];
        se[i] = v;
        out[GG * CC + i] = v;
    }
    __syncthreads();
    for (int i = tid; i < GG * CC; i += blockDim.x) {
        int g = i / CC, c = i % CC;
        float s = lin_b[c];
        const float* e = &se[g * HH];
#pragma unroll 4
        for (int k = 0; k < HH; ++k) s = fmaf(e[k], lin_w[k * CC + c], s);
        out[i] = s;
    }
}

// ---------------- launch ----------------
extern "C" void kernel_launch(void* const* d_in, const int* in_sizes, int n_in,
                              void* d_out, int out_size) {
    const float* x      = (const float*)d_in[0];
    const int*   ei     = (const int*)d_in[1];
    const int*   batch  = (const int*)d_in[2];
    const float* w1r    = (const float*)d_in[3];
    const float* w1rel  = (const float*)d_in[4];
    const float* b1     = (const float*)d_in[5];
    const float* w2r    = (const float*)d_in[6];
    const float* w2rel  = (const float*)d_in[7];
    const float* b2     = (const float*)d_in[8];
    const float* w3     = (const float*)d_in[9];
    const float* b3     = (const float*)d_in[10];
    const float* w4     = (const float*)d_in[11];
    const float* b4     = (const float*)d_in[12];
    const float* w5     = (const float*)d_in[13];
    const float* b5     = (const float*)d_in[14];
    const float* lin_w  = (const float*)d_in[15];
    const float* lin_b  = (const float*)d_in[16];
    float* out = (float*)d_out;

    const int* src = ei;
    const int* dst = ei + EE;

    float *B1, *B2, *B3, *DINV, *EMB, *CNT, *WNORM;
    int *DEG, *ROWS, *CUR, *CSRC;
    cudaGetSymbolAddress((void**)&B1, g_b1);
    cudaGetSymbolAddress((void**)&B2, g_b2);
    cudaGetSymbolAddress((void**)&B3, g_b3);
    cudaGetSymbolAddress((void**)&DINV, g_dinv);
    cudaGetSymbolAddress((void**)&EMB, g_emb);
    cudaGetSymbolAddress((void**)&CNT, g_cnt);
    cudaGetSymbolAddress((void**)&DEG, g_deg);
    cudaGetSymbolAddress((void**)&ROWS, g_rowstart);
    cudaGetSymbolAddress((void**)&CUR, g_cursor);
    cudaGetSymbolAddress((void**)&CSRC, g_csrsrc);
    cudaGetSymbolAddress((void**)&WNORM, g_wnorm);

    const int SMEM = (2 * ASZ + 2 * WSZ) * 4;
    cudaFuncSetAttribute(k_gemm_tc, cudaFuncAttributeMaxDynamicSharedMemorySize, SMEM);

    const int NB  = (NN + 255) / 256;
    const int EB  = (EE + 255) / 256;
    const int GWB = (NN * 32 + 255) / 256;     // gather: warp per node
    const int GMB = (NN + 127) / 128;          // 313

    // ---- CSR build (by destination) ----
    k_zero_int<<<NB, 256>>>(DEG, NN);
    k_hist<<<EB, 256>>>(dst, DEG);
    k_scan<<<1, 1024>>>(DEG, ROWS, CUR, DINV);
    k_fill<<<EB, 256>>>(src, dst, DINV, CUR, CSRC, WNORM);

    // ---- L1: GraphConv ----
    k_gather<<<GWB, 256>>>(x, B1, ROWS, CSRC, nullptr);
    k_gemm_tc<<<GMB, 256, SMEM>>>(x, w1r, B1, w1rel, nullptr, b1, nullptr, B2, nullptr, 1);

    // ---- L2: GraphConv ----
    k_gather<<<GWB, 256>>>(B2, B1, ROWS, CSRC, nullptr);
    k_gemm_tc<<<GMB, 256, SMEM>>>(B2, w2r, B1, w2rel, nullptr, b2, nullptr, B3, nullptr, 1);

    // ---- L3: GCNConv ----  raw h -> B2, self-term h*dinv^2 -> B1; gather adds into B1
    k_gemm_tc<<<GMB, 256, SMEM>>>(B3, w3, nullptr, nullptr, nullptr, nullptr, DINV, B2, B1, 0);
    k_gather<<<GWB, 256>>>(B2, B1, ROWS, CSRC, WNORM);

    // ---- L4: GCNConv (input +b3, relu on load) ----
    k_gemm_tc<<<GMB, 256, SMEM>>>(B1, w4, nullptr, nullptr, b3, nullptr, DINV, B2, B3, 0);
    k_gather<<<GWB, 256>>>(B2, B3, ROWS, CSRC, WNORM);

    // ---- L5: GCNConv (input +b4, relu on load) ----
    k_gemm_tc<<<GMB, 256, SMEM>>>(B3, w5, nullptr, nullptr, b4, nullptr, DINV, B2, B1, 0);
    k_gather<<<GWB, 256>>>(B2, B1, ROWS, CSRC, WNORM);

    // ---- pooling + head (b5 folded into final mean) ----
    k_zero4<<<(GG * HH / 4 + 255) / 256, 256>>>(EMB, GG * HH / 4);
    k_zero4<<<1, 32>>>(CNT, GG / 4);
    k_pool<<<GWB, 256>>>(B1, batch, EMB, CNT);
    k_final<<<1, 512>>>(lin_w, lin_b, b5, EMB, CNT, out);
}